// round 2
// baseline (speedup 1.0000x reference)
#include <cuda_runtime.h>
#include <cstdint>

// Problem constants
#define B_TOT 2048
#define M_    8
#define N_    10
#define C_    10
#define D_    512
#define K_    64
#define W_    512
#define FIN   138
#define P_    80      // M_*N_
#define BT    64      // batch tile per CTA
#define VC    256     // v-chunk width
#define KT    16      // k-tile depth per stage

// Shared memory layout (in floats)
#define SM_H1   0
#define SM_ZC   (64*512)                 // 32768
#define SM_WS   (SM_ZC + 64*128)         // +8192
#define SM_INT  (SM_WS + 2*KT*VC)        // +8192
#define SMEM_FLOATS (SM_INT + 192)
#define SMEM_BYTES  (SMEM_FLOATS * 4)

__device__ __forceinline__ void cp16(float* dst, const float* src) {
    uint32_t s = (uint32_t)__cvta_generic_to_shared(dst);
    asm volatile("cp.async.cg.shared.global [%0], [%1], 16;" :: "r"(s), "l"(src));
}
__device__ __forceinline__ void cp_commit() { asm volatile("cp.async.commit_group;"); }
__device__ __forceinline__ void cp_wait1()  { asm volatile("cp.async.wait_group 1;"); }

__device__ __forceinline__ unsigned long long pk2(float x, float y) {
    unsigned long long r;
    asm("mov.b64 %0, {%1, %2};" : "=l"(r) : "f"(x), "f"(y));
    return r;
}
__device__ __forceinline__ void fma2(unsigned long long& a, unsigned long long x, unsigned long long y) {
    asm("fma.rn.f32x2 %0, %1, %2, %0;" : "+l"(a) : "l"(x), "l"(y));
}
__device__ __forceinline__ float2 up2(unsigned long long v) {
    float2 r;
    asm("mov.b64 {%0, %1}, %2;" : "=f"(r.x), "=f"(r.y) : "l"(v));
    return r;
}

// One (64 x 256) output chunk of A[64 x ksz] @ B[ksz x 512][:, vc:vc+256].
// A is in shared memory (row stride astride). B streamed from global through a
// double-buffered [16][256] smem tile via cp.async. 8b x 8v register tile per
// thread, packed f32x2 accumulators: acc[b][0..1] cover v = vc+lane*4+{0..3},
// acc[b][2..3] cover v = vc+128+lane*4+{0..3}.
template<int KSZ>
__device__ __forceinline__ void gemm_chunk(
    unsigned long long acc[8][4],
    const float* Asm, int astride,
    const float* __restrict__ gsrc,   // [KSZ][512] row-major
    int vc, float* ws, int warp, int lane, int tid)
{
    constexpr int S = KSZ / KT;

    #pragma unroll
    for (int b = 0; b < 8; b++)
        #pragma unroll
        for (int q = 0; q < 4; q++) acc[b][q] = 0ull;

    // prologue: stage 0
    #pragma unroll
    for (int r = 0; r < 4; r++) {
        int i = tid + r * 256;
        int kk = i >> 6, v4 = i & 63;
        cp16(ws + kk * VC + v4 * 4, gsrc + (size_t)kk * W_ + vc + v4 * 4);
    }
    cp_commit();

    for (int s = 0; s < S; s++) {
        if (s + 1 < S) {
            float* wd = ws + ((s + 1) & 1) * (KT * VC);
            const float* gs = gsrc + (size_t)(s + 1) * KT * W_ + vc;
            #pragma unroll
            for (int r = 0; r < 4; r++) {
                int i = tid + r * 256;
                int kk = i >> 6, v4 = i & 63;
                cp16(wd + kk * VC + v4 * 4, gs + (size_t)kk * W_ + v4 * 4);
            }
        }
        cp_commit();            // (possibly empty) group keeps wait-count consistent
        cp_wait1();             // stage s resident
        __syncthreads();

        const float* wb = ws + (s & 1) * (KT * VC);
        const int kbase = s * KT;

        #pragma unroll
        for (int kk = 0; kk < KT; kk += 4) {
            float4 av[8];
            #pragma unroll
            for (int b = 0; b < 8; b++)
                av[b] = *reinterpret_cast<const float4*>(
                    Asm + (size_t)(warp * 8 + b) * astride + kbase + kk);
            #pragma unroll
            for (int kq = 0; kq < 4; kq++) {
                ulonglong2 bv0 = *reinterpret_cast<const ulonglong2*>(wb + (kk + kq) * VC + lane * 4);
                ulonglong2 bv1 = *reinterpret_cast<const ulonglong2*>(wb + (kk + kq) * VC + 128 + lane * 4);
                #pragma unroll
                for (int b = 0; b < 8; b++) {
                    float a = (kq == 0) ? av[b].x : (kq == 1) ? av[b].y : (kq == 2) ? av[b].z : av[b].w;
                    unsigned long long ap = pk2(a, a);
                    fma2(acc[b][0], ap, bv0.x);
                    fma2(acc[b][1], ap, bv0.y);
                    fma2(acc[b][2], ap, bv1.x);
                    fma2(acc[b][3], ap, bv1.y);
                }
            }
        }
        __syncthreads();        // buffer safe to overwrite next iteration
    }
}

extern "C" __global__ void __launch_bounds__(256, 1)
mc_kernel(const int* __restrict__ y, const float* __restrict__ zL, const float* __restrict__ zR,
          const int* __restrict__ idxL, const int* __restrict__ idxR,
          const float* __restrict__ W1, const float* __restrict__ b1,
          const float* __restrict__ W2, const float* __restrict__ b2,
          const float* __restrict__ W3, const float* __restrict__ b3,
          float* __restrict__ out)
{
    extern __shared__ float sm[];
    float* h1 = sm + SM_H1;          // [64][512]
    float* zc = sm + SM_ZC;          // [64][128]
    float* ws = sm + SM_WS;          // [2][16][256]
    int*   ints = (int*)(sm + SM_INT);
    int*   ys   = ints;              // [64]
    int*   idxs = ints + 64;         // [128]

    const int p  = blockIdx.x;                 // pair index m*N + n
    const int m  = p / N_;
    const int n  = p - m * N_;
    const int b0 = blockIdx.y * BT;
    const int tid  = threadIdx.x;
    const int lane = tid & 31;
    const int warp = tid >> 5;

    if (tid < 64)      ys[tid] = y[(size_t)(b0 + tid) * N_ + n];
    else if (tid < 192) {
        int j = tid - 64;
        idxs[j] = (j < 64) ? idxL[m * K_ + j] : idxR[m * K_ + (j - 64)];
    }
    __syncthreads();

    // zcat tile: zc[b][j] = (j<64 ? zL : zR)[b0+b][idx[j]]
    for (int i = tid; i < BT * 128; i += 256) {
        int b = i >> 7, j = i & 127;
        zc[i] = (j < 64) ? zL[(size_t)(b0 + b) * D_ + idxs[j]]
                         : zR[(size_t)(b0 + b) * D_ + idxs[j]];
    }
    // visibility guaranteed by __syncthreads inside gemm_chunk before first compute

    const float* W1p = W1 + (size_t)p * FIN * W_;
    const float* G1  = W1p + (size_t)C_ * W_;          // rows C..C+127: [zL|zR] weights
    const float* b1p = b1 + (size_t)p * W_;
    const float* W2p = W2 + (size_t)p * W_ * W_;
    const float* b2p = b2 + (size_t)p * W_;
    const float* W3p = W3 + (size_t)p * W_;

    unsigned long long acc[8][4];

    // ---------- Phase 1: h1 = relu(zc @ G1 + W1[y] + b1) ----------
    #pragma unroll 1
    for (int vc = 0; vc < W_; vc += VC) {
        gemm_chunk<128>(acc, zc, 128, G1, vc, ws, warp, lane, tid);
        #pragma unroll
        for (int b = 0; b < 8; b++) {
            int row = warp * 8 + b;
            const float* wy = W1p + (size_t)ys[row] * W_;   // one-hot row gather
            #pragma unroll
            for (int g = 0; g < 2; g++) {
                int base = vc + g * 128 + lane * 4;
                float4 ad = *reinterpret_cast<const float4*>(wy + base);
                float4 bb = *reinterpret_cast<const float4*>(b1p + base);
                float2 x0 = up2(acc[b][g * 2 + 0]);
                float2 x1 = up2(acc[b][g * 2 + 1]);
                float4 r;
                r.x = fmaxf(x0.x + ad.x + bb.x, 0.f);
                r.y = fmaxf(x0.y + ad.y + bb.y, 0.f);
                r.z = fmaxf(x1.x + ad.z + bb.z, 0.f);
                r.w = fmaxf(x1.y + ad.w + bb.w, 0.f);
                *reinterpret_cast<float4*>(h1 + (size_t)row * W_ + base) = r;
            }
        }
    }

    // ---------- Phase 2: out = relu(h1 @ W2 + b2) . W3 + b3 (h2 never stored) ----------
    float po[8];
    #pragma unroll
    for (int b = 0; b < 8; b++) po[b] = 0.f;

    #pragma unroll 1
    for (int vc = 0; vc < W_; vc += VC) {
        gemm_chunk<512>(acc, h1, 512, W2p, vc, ws, warp, lane, tid);
        #pragma unroll
        for (int b = 0; b < 8; b++) {
            #pragma unroll
            for (int g = 0; g < 2; g++) {
                int base = vc + g * 128 + lane * 4;
                float4 bb = *reinterpret_cast<const float4*>(b2p + base);
                float4 w3 = *reinterpret_cast<const float4*>(W3p + base);
                float2 x0 = up2(acc[b][g * 2 + 0]);
                float2 x1 = up2(acc[b][g * 2 + 1]);
                po[b] += fmaxf(x0.x + bb.x, 0.f) * w3.x
                       + fmaxf(x0.y + bb.y, 0.f) * w3.y
                       + fmaxf(x1.x + bb.z, 0.f) * w3.z
                       + fmaxf(x1.y + bb.w, 0.f) * w3.w;
            }
        }
    }

    // lanes of a warp share the same 8 batch rows -> butterfly reduce over v
    #pragma unroll
    for (int b = 0; b < 8; b++) {
        #pragma unroll
        for (int off = 16; off; off >>= 1)
            po[b] += __shfl_xor_sync(0xffffffffu, po[b], off);
    }
    if (lane == 0) {
        float bias3 = b3[p];
        #pragma unroll
        for (int b = 0; b < 8; b++)
            out[(size_t)(b0 + warp * 8 + b) * P_ + p] = po[b] + bias3;
    }
}

extern "C" void kernel_launch(void* const* d_in, const int* in_sizes, int n_in,
                              void* d_out, int out_size)
{
    (void)in_sizes; (void)n_in; (void)out_size;
    const int*   y    = (const int*)  d_in[0];
    const float* zL   = (const float*)d_in[1];
    const float* zR   = (const float*)d_in[2];
    const int*   idxL = (const int*)  d_in[3];
    const int*   idxR = (const int*)  d_in[4];
    const float* W1   = (const float*)d_in[5];
    const float* b1   = (const float*)d_in[6];
    const float* W2   = (const float*)d_in[7];
    const float* b2   = (const float*)d_in[8];
    const float* W3   = (const float*)d_in[9];
    const float* b3   = (const float*)d_in[10];
    float* out = (float*)d_out;

    cudaFuncSetAttribute(mc_kernel, cudaFuncAttributeMaxDynamicSharedMemorySize, SMEM_BYTES);
    dim3 grid(P_, B_TOT / BT);
    mc_kernel<<<grid, 256, SMEM_BYTES>>>(y, zL, zR, idxL, idxR, W1, b1, W2, b2, W3, b3, out);
}

// round 4
// speedup vs baseline: 1.3614x; 1.3614x over previous
#include <cuda_runtime.h>
#include <cuda_bf16.h>
#include <cstdint>

// ---------------- problem constants ----------------
#define B_TOT 2048
#define P_    80
#define FIN   138

// ---------------- packed bf16 hi/lo weight images ----------------
// Row layout (64B): [16 bf16 hi][16 bf16 lo] for k-tile of 16, K-major per n row.
// g_w1pk: [p][kt=8][n=512][64B]  = 80*8*512*64  = 20,971,520 B
// g_w2pk: [p][kt=32][n=512][64B] = 80*32*512*64 = 83,886,080 B
__device__ __align__(1024) unsigned char g_w1pk[(size_t)20971520];
__device__ __align__(1024) unsigned char g_w2pk[(size_t)83886080];

// ---------------- smem layout (bytes) ----------------
#define H1STR 1040              // 512 bf16 + 8 pad
#define ZCSTR 272               // 128 bf16 + 8 pad
#define BSTR  80                // 16 hi + 16 lo bf16 + 16B pad
#define BBUF  20480             // 256 rows * 80
#define SM_H1HI 0
#define SM_H1LO 66560
#define SM_ZCHI 133120
#define SM_ZCLO 150528
#define SM_BS   167936          // 2 * BBUF
#define SM_YS   208896          // 64 int
#define SM_IDX  209152          // 128 int
#define SM_B1   209664          // 512 f
#define SM_B2   211712
#define SM_W3   213760
#define SMEM_TOTAL 215808

// ---------------- helpers ----------------
__device__ __forceinline__ void cp16(void* dst, const void* src) {
    uint32_t s = (uint32_t)__cvta_generic_to_shared(dst);
    asm volatile("cp.async.cg.shared.global [%0], [%1], 16;" :: "r"(s), "l"(src));
}
__device__ __forceinline__ void cp_commit() { asm volatile("cp.async.commit_group;"); }
__device__ __forceinline__ void cp_wait1()  { asm volatile("cp.async.wait_group 1;"); }

__device__ __forceinline__ void mma_bf16(float* c, const uint32_t* a, const uint32_t* b) {
    asm volatile(
        "mma.sync.aligned.m16n8k16.row.col.f32.bf16.bf16.f32 "
        "{%0,%1,%2,%3}, {%4,%5,%6,%7}, {%8,%9}, {%0,%1,%2,%3};"
        : "+f"(c[0]), "+f"(c[1]), "+f"(c[2]), "+f"(c[3])
        : "r"(a[0]), "r"(a[1]), "r"(a[2]), "r"(a[3]), "r"(b[0]), "r"(b[1]));
}
__device__ __forceinline__ uint32_t pkbf(float x0, float x1) {
    __nv_bfloat162 v = __floats2bfloat162_rn(x0, x1);
    return *reinterpret_cast<uint32_t*>(&v);
}
__device__ __forceinline__ void split2(float x0, float x1, uint32_t& hi, uint32_t& lo) {
    __nv_bfloat16 h0 = __float2bfloat16(x0), h1 = __float2bfloat16(x1);
    hi = (uint32_t)__bfloat16_as_ushort(h0) | ((uint32_t)__bfloat16_as_ushort(h1) << 16);
    __nv_bfloat16 l0 = __float2bfloat16(x0 - __bfloat162float(h0));
    __nv_bfloat16 l1 = __float2bfloat16(x1 - __bfloat162float(h1));
    lo = (uint32_t)__bfloat16_as_ushort(l0) | ((uint32_t)__bfloat16_as_ushort(l1) << 16);
}

// ---------------- core GEMM: acc(64x256) += A(64xK) * B(Kx256), 3-pass hi/lo ----
// A in smem (hi/lo bases, padded stride). B streamed from packed global rows via
// double-buffered cp.async stages of one k16 tile ([256 n][16 k] hi+lo).
template<int NST>
__device__ __forceinline__ void gemm3p(
    float acc[2][8][4], char* sm, int ahi, int alo, int astride,
    const unsigned char* __restrict__ gsrc,
    int tid, int mbase, int nbase, int lr, int lcb)
{
    char* bs = sm + SM_BS;
    #pragma unroll
    for (int r = 0; r < 4; r++)
        cp16(bs + tid * BSTR + r * 16, gsrc + tid * 64 + r * 16);
    cp_commit();

    for (int s = 0; s < NST; s++) {
        if (s + 1 < NST) {
            char* wd = bs + ((s + 1) & 1) * BBUF;
            const unsigned char* g = gsrc + (size_t)(s + 1) * 32768;
            #pragma unroll
            for (int r = 0; r < 4; r++)
                cp16(wd + tid * BSTR + r * 16, g + tid * 64 + r * 16);
        }
        cp_commit();
        cp_wait1();
        __syncthreads();

        const char* wb = bs + (s & 1) * BBUF;
        const int kb2 = s * 32;          // k offset in bytes (16 bf16)

        uint32_t ah[2][4], al[2][4];
        #pragma unroll
        for (int mt = 0; mt < 2; mt++) {
            const char* ab = sm + ahi + (size_t)(mbase + mt * 16 + lr) * astride + kb2 + lcb;
            const char* lb = sm + alo + (size_t)(mbase + mt * 16 + lr) * astride + kb2 + lcb;
            ah[mt][0] = *(const uint32_t*)(ab);
            ah[mt][1] = *(const uint32_t*)(ab + 8 * astride);
            ah[mt][2] = *(const uint32_t*)(ab + 16);
            ah[mt][3] = *(const uint32_t*)(ab + 8 * astride + 16);
            al[mt][0] = *(const uint32_t*)(lb);
            al[mt][1] = *(const uint32_t*)(lb + 8 * astride);
            al[mt][2] = *(const uint32_t*)(lb + 16);
            al[mt][3] = *(const uint32_t*)(lb + 8 * astride + 16);
        }
        #pragma unroll
        for (int nt = 0; nt < 8; nt++) {
            const char* bb = wb + (nbase + nt * 8 + lr) * BSTR + lcb;
            uint32_t bh[2], bl[2];
            bh[0] = *(const uint32_t*)(bb);
            bh[1] = *(const uint32_t*)(bb + 16);
            bl[0] = *(const uint32_t*)(bb + 32);
            bl[1] = *(const uint32_t*)(bb + 48);
            mma_bf16(acc[0][nt], ah[0], bh);
            mma_bf16(acc[1][nt], ah[1], bh);
            mma_bf16(acc[0][nt], al[0], bh);
            mma_bf16(acc[1][nt], al[1], bh);
            mma_bf16(acc[0][nt], ah[0], bl);
            mma_bf16(acc[1][nt], ah[1], bl);
        }
        __syncthreads();
    }
}

// ---------------- prep: fp32 weights -> packed K-major hi/lo rows ----------------
extern "C" __global__ void __launch_bounds__(256)
prep_kernel(const float* __restrict__ W1, const float* __restrict__ W2)
{
    int j = blockIdx.x;
    const float* src;
    unsigned char* dst;
    if (j < 640) {                           // W1 zc-part: p, kt(8)
        int p = j >> 3, kt = j & 7;
        src = W1 + ((size_t)p * FIN + 10 + kt * 16) * 512;
        dst = g_w1pk + (size_t)p * 262144 + (size_t)kt * 32768;
    } else {                                 // W2: p, kt(32)
        int q = j - 640;
        int p = q >> 5, kt = q & 31;
        src = W2 + ((size_t)p * 512 + kt * 16) * 512;
        dst = g_w2pk + (size_t)p * 1048576 + (size_t)kt * 32768;
    }
    for (int n = threadIdx.x; n < 512; n += 256) {
        uint32_t hi[8], lo[8];
        #pragma unroll
        for (int kk = 0; kk < 8; kk++) {
            float v0 = src[(size_t)(2 * kk) * 512 + n];
            float v1 = src[(size_t)(2 * kk + 1) * 512 + n];
            split2(v0, v1, hi[kk], lo[kk]);
        }
        uint4* d = (uint4*)(dst + (size_t)n * 64);
        d[0] = make_uint4(hi[0], hi[1], hi[2], hi[3]);
        d[1] = make_uint4(hi[4], hi[5], hi[6], hi[7]);
        d[2] = make_uint4(lo[0], lo[1], lo[2], lo[3]);
        d[3] = make_uint4(lo[4], lo[5], lo[6], lo[7]);
    }
}

extern "C" __global__ void init_out(const float* __restrict__ b3, float* __restrict__ out)
{
    int i = blockIdx.x * 256 + threadIdx.x;
    if (i < B_TOT * P_) out[i] = b3[i % P_];
}

// ---------------- main ----------------
extern "C" __global__ void __launch_bounds__(256, 1)
mc_main(const int* __restrict__ y, const float* __restrict__ zL, const float* __restrict__ zR,
        const int* __restrict__ idxL, const int* __restrict__ idxR,
        const float* __restrict__ W1, const float* __restrict__ b1,
        const float* __restrict__ b2, const float* __restrict__ W3,
        float* __restrict__ out)
{
    extern __shared__ char sm[];
    int*   ys   = (int*)(sm + SM_YS);
    int*   idxs = (int*)(sm + SM_IDX);
    float* b1s  = (float*)(sm + SM_B1);
    float* b2s  = (float*)(sm + SM_B2);
    float* w3s  = (float*)(sm + SM_W3);

    const int p = blockIdx.x, b0 = blockIdx.y * 64;
    const int m = p / 10, nn = p - m * 10;
    const int tid = threadIdx.x, l = tid & 31, w = tid >> 5;
    const int mbase = (w >> 2) * 32, nbase = (w & 3) * 64;
    const int lr = l >> 2, lcb = (l & 3) * 4;

    if (tid < 64)  ys[tid] = y[(size_t)(b0 + tid) * 10 + nn];
    if (tid < 128) idxs[tid] = (tid < 64) ? idxL[m * 64 + tid] : idxR[m * 64 + (tid - 64)];
    for (int i = tid; i < 512; i += 256) {
        b1s[i] = b1[(size_t)p * 512 + i];
        b2s[i] = b2[(size_t)p * 512 + i];
        w3s[i] = W3[(size_t)p * 512 + i];
    }
    __syncthreads();

    // zc gather + split (rows = batch, cols = 128 features)
    {
        int row = tid >> 2, cb = (tid & 3) * 32;
        const float* zl = zL + (size_t)(b0 + row) * 512;
        const float* zr = zR + (size_t)(b0 + row) * 512;
        uint32_t* hid = (uint32_t*)(sm + SM_ZCHI + (size_t)row * ZCSTR + cb * 2);
        uint32_t* lod = (uint32_t*)(sm + SM_ZCLO + (size_t)row * ZCSTR + cb * 2);
        #pragma unroll
        for (int jp = 0; jp < 16; jp++) {
            int j0 = cb + jp * 2;
            float v0 = (j0 < 64) ? zl[idxs[j0]] : zr[idxs[j0]];
            float v1 = (j0 + 1 < 64) ? zl[idxs[j0 + 1]] : zr[idxs[j0 + 1]];
            uint32_t hi, lo;
            split2(v0, v1, hi, lo);
            hid[jp] = hi; lod[jp] = lo;
        }
    }
    // visibility: first __syncthreads inside gemm3p precedes all compute

    float acc[2][8][4];
    const unsigned char* g1 = g_w1pk + (size_t)p * 262144;
    const float* W1p = W1 + (size_t)p * FIN * 512;

    // ---------- layer 1 ----------
    #pragma unroll 1
    for (int nc = 0; nc < 2; nc++) {
        #pragma unroll
        for (int a = 0; a < 2; a++)
            #pragma unroll
            for (int b = 0; b < 8; b++)
                #pragma unroll
                for (int q = 0; q < 4; q++) acc[a][b][q] = 0.f;

        gemm3p<8>(acc, sm, SM_ZCHI, SM_ZCLO, ZCSTR, g1 + nc * 16384,
                  tid, mbase, nbase, lr, lcb);

        #pragma unroll
        for (int mt = 0; mt < 2; mt++) {
            int r0 = mbase + mt * 16 + lr;
            const float* wy0 = W1p + (size_t)ys[r0] * 512;
            const float* wy1 = W1p + (size_t)ys[r0 + 8] * 512;
            #pragma unroll
            for (int nt = 0; nt < 8; nt++) {
                int col = nc * 256 + nbase + nt * 8 + (l & 3) * 2;
                float2 bv = *(const float2*)(b1s + col);
                float x0 = fmaxf(acc[mt][nt][0] + wy0[col]     + bv.x, 0.f);
                float x1 = fmaxf(acc[mt][nt][1] + wy0[col + 1] + bv.y, 0.f);
                float x2 = fmaxf(acc[mt][nt][2] + wy1[col]     + bv.x, 0.f);
                float x3 = fmaxf(acc[mt][nt][3] + wy1[col + 1] + bv.y, 0.f);
                uint32_t hi, lo;
                split2(x0, x1, hi, lo);
                *(uint32_t*)(sm + SM_H1HI + (size_t)r0 * H1STR + col * 2) = hi;
                *(uint32_t*)(sm + SM_H1LO + (size_t)r0 * H1STR + col * 2) = lo;
                split2(x2, x3, hi, lo);
                *(uint32_t*)(sm + SM_H1HI + (size_t)(r0 + 8) * H1STR + col * 2) = hi;
                *(uint32_t*)(sm + SM_H1LO + (size_t)(r0 + 8) * H1STR + col * 2) = lo;
            }
        }
    }
    // h1 visibility for cross-warp reads: first __syncthreads inside next gemm3p

    // ---------- layer 2 + fused W3 ----------
    const unsigned char* g2 = g_w2pk + (size_t)p * 1048576;
    float po[2][2] = {{0.f, 0.f}, {0.f, 0.f}};

    #pragma unroll 1
    for (int nc = 0; nc < 2; nc++) {
        #pragma unroll
        for (int a = 0; a < 2; a++)
            #pragma unroll
            for (int b = 0; b < 8; b++)
                #pragma unroll
                for (int q = 0; q < 4; q++) acc[a][b][q] = 0.f;

        gemm3p<32>(acc, sm, SM_H1HI, SM_H1LO, H1STR, g2 + nc * 16384,
                   tid, mbase, nbase, lr, lcb);

        #pragma unroll
        for (int mt = 0; mt < 2; mt++) {
            #pragma unroll
            for (int nt = 0; nt < 8; nt++) {
                int col = nc * 256 + nbase + nt * 8 + (l & 3) * 2;
                float2 bv = *(const float2*)(b2s + col);
                float2 wv = *(const float2*)(w3s + col);
                po[mt][0] += fmaxf(acc[mt][nt][0] + bv.x, 0.f) * wv.x
                           + fmaxf(acc[mt][nt][1] + bv.y, 0.f) * wv.y;
                po[mt][1] += fmaxf(acc[mt][nt][2] + bv.x, 0.f) * wv.x
                           + fmaxf(acc[mt][nt][3] + bv.y, 0.f) * wv.y;
            }
        }
    }

    #pragma unroll
    for (int mt = 0; mt < 2; mt++)
        #pragma unroll
        for (int h = 0; h < 2; h++) {
            float v = po[mt][h];
            v += __shfl_xor_sync(0xffffffffu, v, 1);
            v += __shfl_xor_sync(0xffffffffu, v, 2);
            if ((l & 3) == 0) {
                int row = mbase + mt * 16 + lr + h * 8;
                atomicAdd(out + (size_t)(b0 + row) * P_ + p, v);
            }
        }
}

// ---------------- host ----------------
extern "C" void kernel_launch(void* const* d_in, const int* in_sizes, int n_in,
                              void* d_out, int out_size)
{
    (void)in_sizes; (void)n_in; (void)out_size;
    const int*   y    = (const int*)  d_in[0];
    const float* zL   = (const float*)d_in[1];
    const float* zR   = (const float*)d_in[2];
    const int*   idxL = (const int*)  d_in[3];
    const int*   idxR = (const int*)  d_in[4];
    const float* W1   = (const float*)d_in[5];
    const float* b1   = (const float*)d_in[6];
    const float* W2   = (const float*)d_in[7];
    const float* b2   = (const float*)d_in[8];
    const float* W3   = (const float*)d_in[9];
    const float* b3   = (const float*)d_in[10];
    float* out = (float*)d_out;

    cudaFuncSetAttribute(mc_main, cudaFuncAttributeMaxDynamicSharedMemorySize, SMEM_TOTAL);

    prep_kernel<<<3200, 256>>>(W1, W2);
    init_out<<<(B_TOT * P_ + 255) / 256, 256>>>(b3, out);
    dim3 grid(P_, B_TOT / 64);
    mc_main<<<grid, 256, SMEM_TOTAL>>>(y, zL, zR, idxL, idxR, W1, b1, b2, W3, out);
}

// round 5
// speedup vs baseline: 2.0444x; 1.5017x over previous
#include <cuda_runtime.h>
#include <cuda_bf16.h>
#include <cstdint>

// ---------------- problem constants ----------------
#define B_TOT 2048
#define P_    80
#define FIN   138

// ---------------- packed bf16 hi/lo weight images ----------------
// Row = 128B: [32 bf16 hi][32 bf16 lo] per k32 tile, K-major per n row.
// g_w1pk: [p][kt=4][n=512][128B]  = 20,971,520 B
// g_w2pk: [p][kt=16][n=512][128B] = 83,886,080 B
__device__ __align__(1024) unsigned char g_w1pk[(size_t)20971520];
__device__ __align__(1024) unsigned char g_w2pk[(size_t)83886080];

// ---------------- smem layout (bytes) ----------------
#define H1STR 1040                  // 512 bf16 (1024B) + 16 pad
#define BSTR  144                   // 64B hi + 64B lo + 16 pad
#define BBUF  36864                 // 256 rows * 144
#define SM_H1HI 0                   // 64*1040 ; zc-hi lives at +512 in each row
#define SM_H1LO 66560               // 64*1040 ; zc-lo lives at +512 in each row
#define SM_BS   133120              // 2 * BBUF = 73728
#define SM_YS   206848
#define SM_IDX  207104
#define SM_B1   207616
#define SM_B2   209664
#define SM_W3   211712
#define SMEM_TOTAL 213760

// ---------------- helpers ----------------
__device__ __forceinline__ void cp16s(uint32_t dst, const void* src) {
    asm volatile("cp.async.cg.shared.global [%0], [%1], 16;" :: "r"(dst), "l"(src));
}
__device__ __forceinline__ void cp_commit() { asm volatile("cp.async.commit_group;"); }
__device__ __forceinline__ void cp_wait0()  { asm volatile("cp.async.wait_group 0;"); }

__device__ __forceinline__ void ldsm4(uint32_t* r, uint32_t addr) {
    asm volatile("ldmatrix.sync.aligned.m8n8.x4.shared.b16 {%0,%1,%2,%3}, [%4];"
        : "=r"(r[0]), "=r"(r[1]), "=r"(r[2]), "=r"(r[3]) : "r"(addr));
}
__device__ __forceinline__ void mma_bf16(float* c, const uint32_t* a, const uint32_t* b) {
    asm volatile(
        "mma.sync.aligned.m16n8k16.row.col.f32.bf16.bf16.f32 "
        "{%0,%1,%2,%3}, {%4,%5,%6,%7}, {%8,%9}, {%0,%1,%2,%3};"
        : "+f"(c[0]), "+f"(c[1]), "+f"(c[2]), "+f"(c[3])
        : "r"(a[0]), "r"(a[1]), "r"(a[2]), "r"(a[3]), "r"(b[0]), "r"(b[1]));
}
__device__ __forceinline__ void split2(float x0, float x1, uint32_t& hi, uint32_t& lo) {
    __nv_bfloat16 h0 = __float2bfloat16(x0), h1 = __float2bfloat16(x1);
    hi = (uint32_t)__bfloat16_as_ushort(h0) | ((uint32_t)__bfloat16_as_ushort(h1) << 16);
    __nv_bfloat16 l0 = __float2bfloat16(x0 - __bfloat162float(h0));
    __nv_bfloat16 l1 = __float2bfloat16(x1 - __bfloat162float(h1));
    lo = (uint32_t)__bfloat16_as_ushort(l0) | ((uint32_t)__bfloat16_as_ushort(l1) << 16);
}

// ---------------- core GEMM: acc(64x256) += A(64x32*NST) * B, 3-pass hi/lo -------
// A fragments via ldmatrix from smem (aHi/aLo = per-lane base addrs incl. row/lane
// offsets). B streamed from packed global rows ([n][32hi|32lo]) via double-buffered
// k32 stages; ONE barrier per stage (prefetch issued after the barrier).
template<int NST>
__device__ __forceinline__ void gemm3p(
    float acc[2][8][4], uint32_t aHi, uint32_t aLo,
    uint32_t bBase, uint32_t bsWrite,
    const unsigned char* __restrict__ gsrc, int tid)
{
    // prologue: stage 0
    #pragma unroll
    for (int r = 0; r < 8; r++) {
        int i = tid + r * 256;
        cp16s(bsWrite + (uint32_t)((i >> 3) * BSTR + (i & 7) * 16), gsrc + (size_t)i * 16);
    }
    cp_commit();

    #pragma unroll 1
    for (int s = 0; s < NST; s++) {
        cp_wait0();
        __syncthreads();
        if (s + 1 < NST) {
            uint32_t wd = bsWrite + (uint32_t)(((s + 1) & 1) * BBUF);
            const unsigned char* g = gsrc + (size_t)(s + 1) * 65536;
            #pragma unroll
            for (int r = 0; r < 8; r++) {
                int i = tid + r * 256;
                cp16s(wd + (uint32_t)((i >> 3) * BSTR + (i & 7) * 16), g + (size_t)i * 16);
            }
            cp_commit();
        }

        const uint32_t bb = bBase + (uint32_t)((s & 1) * BBUF);
        const uint32_t ka = (uint32_t)(s * 64);

        #pragma unroll
        for (int t = 0; t < 2; t++) {
            uint32_t ah[2][4], al[2][4];
            #pragma unroll
            for (int mt = 0; mt < 2; mt++) {
                ldsm4(ah[mt], aHi + (uint32_t)(mt * 16 * H1STR) + ka + t * 32);
                ldsm4(al[mt], aLo + (uint32_t)(mt * 16 * H1STR) + ka + t * 32);
            }
            uint32_t bh[4][4], bl[4][4];
            #pragma unroll
            for (int q = 0; q < 4; q++) {
                uint32_t ba = bb + (uint32_t)(q * 16 * BSTR) + (uint32_t)(t * 32);
                ldsm4(bh[q], ba);
                ldsm4(bl[q], ba + 64);
            }
            #pragma unroll
            for (int nt = 0; nt < 8; nt++) {
                const uint32_t* bhf = &bh[nt >> 1][(nt & 1) * 2];
                const uint32_t* blf = &bl[nt >> 1][(nt & 1) * 2];
                mma_bf16(acc[0][nt], ah[0], bhf);
                mma_bf16(acc[1][nt], ah[1], bhf);
                mma_bf16(acc[0][nt], al[0], bhf);
                mma_bf16(acc[1][nt], al[1], bhf);
                mma_bf16(acc[0][nt], ah[0], blf);
                mma_bf16(acc[1][nt], ah[1], blf);
            }
        }
    }
}

// ---------------- prep: fp32 weights -> packed K-major hi/lo k32 rows ------------
extern "C" __global__ void __launch_bounds__(256)
prep_kernel(const float* __restrict__ W1, const float* __restrict__ W2)
{
    int j = blockIdx.x;
    const float* src;
    unsigned char* dst;
    if (j < 320) {                           // W1 zc-part: (p, kt=4)
        int p = j >> 2, kt = j & 3;
        src = W1 + ((size_t)p * FIN + 10 + kt * 32) * 512;
        dst = g_w1pk + (size_t)p * 262144 + (size_t)kt * 65536;
    } else {                                 // W2: (p, kt=16)
        int q = j - 320;
        int p = q >> 4, kt = q & 15;
        src = W2 + ((size_t)p * 512 + kt * 32) * 512;
        dst = g_w2pk + (size_t)p * 1048576 + (size_t)kt * 65536;
    }
    for (int n = threadIdx.x; n < 512; n += 256) {
        uint32_t hi[16], lo[16];
        #pragma unroll
        for (int kk = 0; kk < 16; kk++) {
            float v0 = src[(size_t)(2 * kk) * 512 + n];
            float v1 = src[(size_t)(2 * kk + 1) * 512 + n];
            split2(v0, v1, hi[kk], lo[kk]);
        }
        uint4* d = (uint4*)(dst + (size_t)n * 128);
        #pragma unroll
        for (int r = 0; r < 4; r++)
            d[r] = make_uint4(hi[r * 4], hi[r * 4 + 1], hi[r * 4 + 2], hi[r * 4 + 3]);
        #pragma unroll
        for (int r = 0; r < 4; r++)
            d[4 + r] = make_uint4(lo[r * 4], lo[r * 4 + 1], lo[r * 4 + 2], lo[r * 4 + 3]);
    }
}

extern "C" __global__ void init_out(const float* __restrict__ b3, float* __restrict__ out)
{
    int i = blockIdx.x * 256 + threadIdx.x;
    if (i < B_TOT * P_) out[i] = b3[i % P_];
}

// ---------------- main ----------------
extern "C" __global__ void __launch_bounds__(256, 1)
mc_main(const int* __restrict__ y, const float* __restrict__ zL, const float* __restrict__ zR,
        const int* __restrict__ idxL, const int* __restrict__ idxR,
        const float* __restrict__ W1, const float* __restrict__ b1,
        const float* __restrict__ b2, const float* __restrict__ W3,
        float* __restrict__ out)
{
    extern __shared__ char sm[];
    const uint32_t smb = (uint32_t)__cvta_generic_to_shared(sm);
    int*   ys   = (int*)(sm + SM_YS);
    int*   idxs = (int*)(sm + SM_IDX);
    float* b1s  = (float*)(sm + SM_B1);
    float* b2s  = (float*)(sm + SM_B2);
    float* w3s  = (float*)(sm + SM_W3);

    const int p = blockIdx.x, b0 = blockIdx.y * 64;
    const int m = p / 10, nn = p - m * 10;
    const int tid = threadIdx.x, l = tid & 31, w = tid >> 5;
    const int mbase = (w >> 2) * 32, nbase = (w & 3) * 64;
    const int lr = l >> 2;

    if (tid < 64)  ys[tid] = y[(size_t)(b0 + tid) * 10 + nn];
    if (tid < 128) idxs[tid] = (tid < 64) ? idxL[m * 64 + tid] : idxR[m * 64 + (tid - 64)];
    for (int i = tid; i < 512; i += 256) {
        b1s[i] = b1[(size_t)p * 512 + i];
        b2s[i] = b2[(size_t)p * 512 + i];
        w3s[i] = W3[(size_t)p * 512 + i];
    }
    __syncthreads();

    // zc gather + split into the h1 column-tail region (bytes 512..767 of each row)
    {
        int row = tid >> 2, cb = (tid & 3) * 32;
        const float* zl = zL + (size_t)(b0 + row) * 512;
        const float* zr = zR + (size_t)(b0 + row) * 512;
        uint32_t* hid = (uint32_t*)(sm + SM_H1HI + (size_t)row * H1STR + 512 + cb * 2);
        uint32_t* lod = (uint32_t*)(sm + SM_H1LO + (size_t)row * H1STR + 512 + cb * 2);
        #pragma unroll
        for (int jp = 0; jp < 16; jp++) {
            int j0 = cb + jp * 2;
            float v0 = (j0 < 64) ? zl[idxs[j0]] : zr[idxs[j0]];
            float v1 = (j0 + 1 < 64) ? zl[idxs[j0 + 1]] : zr[idxs[j0 + 1]];
            uint32_t hi, lo;
            split2(v0, v1, hi, lo);
            hid[jp] = hi; lod[jp] = lo;
        }
    }
    // visibility: first in-gemm __syncthreads precedes all ldsm reads

    // per-lane ldmatrix base addresses
    const uint32_t aRowOff = (uint32_t)((mbase + (l & 15)) * H1STR + (l >> 4) * 16);
    const uint32_t aHi1 = smb + SM_H1HI + 512 + aRowOff;   // zc (layer 1)
    const uint32_t aLo1 = smb + SM_H1LO + 512 + aRowOff;
    const uint32_t aHi2 = smb + SM_H1HI + aRowOff;         // h1 (layer 2)
    const uint32_t aLo2 = smb + SM_H1LO + aRowOff;
    const uint32_t bBase = smb + SM_BS +
        (uint32_t)((nbase + (l & 7) + ((l >> 4) << 3)) * BSTR + ((l >> 3) & 1) * 16);
    const uint32_t bsWrite = smb + SM_BS;

    float acc[2][8][4];
    const unsigned char* g1 = g_w1pk + (size_t)p * 262144;
    const float* W1p = W1 + (size_t)p * FIN * 512;

    // ---------- layer 1 ----------
    #pragma unroll 1
    for (int nc = 0; nc < 2; nc++) {
        #pragma unroll
        for (int a = 0; a < 2; a++)
            #pragma unroll
            for (int b = 0; b < 8; b++)
                #pragma unroll
                for (int q = 0; q < 4; q++) acc[a][b][q] = 0.f;

        gemm3p<4>(acc, aHi1, aLo1, bBase, bsWrite, g1 + nc * 32768, tid);
        __syncthreads();   // zc reads (above) complete before h1-tail writes below

        #pragma unroll
        for (int mt = 0; mt < 2; mt++) {
            int r0 = mbase + mt * 16 + lr;
            const float* wy0 = W1p + (size_t)ys[r0] * 512;
            const float* wy1 = W1p + (size_t)ys[r0 + 8] * 512;
            #pragma unroll
            for (int nt = 0; nt < 8; nt++) {
                int col = nc * 256 + nbase + nt * 8 + (l & 3) * 2;
                float2 bv = *(const float2*)(b1s + col);
                float x0 = fmaxf(acc[mt][nt][0] + wy0[col]     + bv.x, 0.f);
                float x1 = fmaxf(acc[mt][nt][1] + wy0[col + 1] + bv.y, 0.f);
                float x2 = fmaxf(acc[mt][nt][2] + wy1[col]     + bv.x, 0.f);
                float x3 = fmaxf(acc[mt][nt][3] + wy1[col + 1] + bv.y, 0.f);
                uint32_t hi, lo;
                split2(x0, x1, hi, lo);
                *(uint32_t*)(sm + SM_H1HI + (size_t)r0 * H1STR + col * 2) = hi;
                *(uint32_t*)(sm + SM_H1LO + (size_t)r0 * H1STR + col * 2) = lo;
                split2(x2, x3, hi, lo);
                *(uint32_t*)(sm + SM_H1HI + (size_t)(r0 + 8) * H1STR + col * 2) = hi;
                *(uint32_t*)(sm + SM_H1LO + (size_t)(r0 + 8) * H1STR + col * 2) = lo;
            }
        }
    }
    // h1 visibility: first in-gemm __syncthreads of layer 2

    // ---------- layer 2 + fused W3 ----------
    const unsigned char* g2 = g_w2pk + (size_t)p * 1048576;
    float po[2][2] = {{0.f, 0.f}, {0.f, 0.f}};

    #pragma unroll 1
    for (int nc = 0; nc < 2; nc++) {
        #pragma unroll
        for (int a = 0; a < 2; a++)
            #pragma unroll
            for (int b = 0; b < 8; b++)
                #pragma unroll
                for (int q = 0; q < 4; q++) acc[a][b][q] = 0.f;

        gemm3p<16>(acc, aHi2, aLo2, bBase, bsWrite, g2 + nc * 32768, tid);

        #pragma unroll
        for (int mt = 0; mt < 2; mt++) {
            #pragma unroll
            for (int nt = 0; nt < 8; nt++) {
                int col = nc * 256 + nbase + nt * 8 + (l & 3) * 2;
                float2 bv = *(const float2*)(b2s + col);
                float2 wv = *(const float2*)(w3s + col);
                po[mt][0] += fmaxf(acc[mt][nt][0] + bv.x, 0.f) * wv.x
                           + fmaxf(acc[mt][nt][1] + bv.y, 0.f) * wv.y;
                po[mt][1] += fmaxf(acc[mt][nt][2] + bv.x, 0.f) * wv.x
                           + fmaxf(acc[mt][nt][3] + bv.y, 0.f) * wv.y;
            }
        }
    }

    #pragma unroll
    for (int mt = 0; mt < 2; mt++)
        #pragma unroll
        for (int h = 0; h < 2; h++) {
            float v = po[mt][h];
            v += __shfl_xor_sync(0xffffffffu, v, 1);
            v += __shfl_xor_sync(0xffffffffu, v, 2);
            if ((l & 3) == 0) {
                int row = mbase + mt * 16 + lr + h * 8;
                atomicAdd(out + (size_t)(b0 + row) * P_ + p, v);
            }
        }
}

// ---------------- host ----------------
extern "C" void kernel_launch(void* const* d_in, const int* in_sizes, int n_in,
                              void* d_out, int out_size)
{
    (void)in_sizes; (void)n_in; (void)out_size;
    const int*   y    = (const int*)  d_in[0];
    const float* zL   = (const float*)d_in[1];
    const float* zR   = (const float*)d_in[2];
    const int*   idxL = (const int*)  d_in[3];
    const int*   idxR = (const int*)  d_in[4];
    const float* W1   = (const float*)d_in[5];
    const float* b1   = (const float*)d_in[6];
    const float* W2   = (const float*)d_in[7];
    const float* b2   = (const float*)d_in[8];
    const float* W3   = (const float*)d_in[9];
    const float* b3   = (const float*)d_in[10];
    float* out = (float*)d_out;

    cudaFuncSetAttribute(mc_main, cudaFuncAttributeMaxDynamicSharedMemorySize, SMEM_TOTAL);

    prep_kernel<<<1600, 256>>>(W1, W2);
    init_out<<<(B_TOT * P_ + 255) / 256, 256>>>(b3, out);
    dim3 grid(P_, B_TOT / 64);
    mc_main<<<grid, 256, SMEM_TOTAL>>>(y, zL, zR, idxL, idxR, W1, b1, b2, W3, out);
}